// round 15
// baseline (speedup 1.0000x reference)
#include <cuda_runtime.h>
#include <cuda_fp16.h>
#include <cstdint>

#define N_SP 4096
#define C_CH 512
#define B_SZ 4

typedef unsigned long long u64;
typedef unsigned int u32;

__device__ __half g_xth[(size_t)B_SZ * N_SP * C_CH];
__device__ __half g_xtl[(size_t)B_SZ * N_SP * C_CH];
__device__ __half g_wqh[64 * C_CH], g_wql[64 * C_CH];
__device__ __half g_wkh[64 * C_CH], g_wkl[64 * C_CH];
__device__ __half g_wvh[C_CH * C_CH], g_wvl[C_CH * C_CH];
__device__ __half g_qh[(size_t)B_SZ * N_SP * 64];
__device__ __half g_ql[(size_t)B_SZ * N_SP * 64];
__device__ __half g_kh[(size_t)B_SZ * N_SP * 64];
__device__ __half g_kl[(size_t)B_SZ * N_SP * 64];
__device__ __half g_vh[(size_t)B_SZ * C_CH * N_SP];
__device__ float  g_S [(size_t)B_SZ * N_SP * N_SP];
__device__ __half g_P [(size_t)B_SZ * N_SP * N_SP];
__device__ float  g_l [(size_t)B_SZ * N_SP];

__device__ __forceinline__ u32 s2u(const void* p) { return (u32)__cvta_generic_to_shared(p); }
__device__ __forceinline__ void cp16(u32 d, const void* s) {
    asm volatile("cp.async.cg.shared.global [%0], [%1], 16;" :: "r"(d), "l"(s));
}
__device__ __forceinline__ void cp_commit() { asm volatile("cp.async.commit_group;"); }
__device__ __forceinline__ void cp_wait0()  { asm volatile("cp.async.wait_group 0;"); }
__device__ __forceinline__ void cp_wait1()  { asm volatile("cp.async.wait_group 1;"); }
__device__ __forceinline__ u32 sw128(u32 o) { return o ^ ((o >> 3) & 0x70); }

__device__ __forceinline__ void ldsm4(u32& r0, u32& r1, u32& r2, u32& r3, u32 a) {
    asm volatile("ldmatrix.sync.aligned.m8n8.x4.shared.b16 {%0,%1,%2,%3}, [%4];"
                 : "=r"(r0), "=r"(r1), "=r"(r2), "=r"(r3) : "r"(a));
}
__device__ __forceinline__ void ldsm2(u32& r0, u32& r1, u32 a) {
    asm volatile("ldmatrix.sync.aligned.m8n8.x2.shared.b16 {%0,%1}, [%2];"
                 : "=r"(r0), "=r"(r1) : "r"(a));
}
__device__ __forceinline__ void mma16816(float* d, const u32* a, const u32* b) {
    asm volatile("mma.sync.aligned.m16n8k16.row.col.f32.f16.f16.f32 "
                 "{%0,%1,%2,%3}, {%4,%5,%6,%7}, {%8,%9}, {%0,%1,%2,%3};"
                 : "+f"(d[0]), "+f"(d[1]), "+f"(d[2]), "+f"(d[3])
                 : "r"(a[0]), "r"(a[1]), "r"(a[2]), "r"(a[3]), "r"(b[0]), "r"(b[1]));
}
__device__ __forceinline__ void st_hl2(__half* ph, __half* pl, size_t a, float o0, float o1) {
    __half h0 = __float2half_rn(o0), h1 = __float2half_rn(o1);
    __half l0 = __float2half_rn(o0 - __half2float(h0));
    __half l1 = __float2half_rn(o1 - __half2float(h1));
    *(__half2*)(ph + a) = __halves2half2(h0, h1);
    *(__half2*)(pl + a) = __halves2half2(l0, l1);
}

// ---------------------------------------------------------------------------
// conv (merged): blocks 0..8191 transpose+split x; 8192..9471 split weights
// ---------------------------------------------------------------------------
__global__ __launch_bounds__(256) void conv_kernel(
    const float* __restrict__ x, const float* __restrict__ wq,
    const float* __restrict__ wk, const float* __restrict__ wv)
{
    __shared__ float tile[32][33];
    int bid = blockIdx.x;
    if (bid < 8192) {
        int tx = threadIdx.x & 31, ty = threadIdx.x >> 5;
        int n0 = (bid & 127) * 32, c0 = ((bid >> 7) & 15) * 32, b = bid >> 11;
#pragma unroll
        for (int k = 0; k < 4; k++)
            tile[ty + k * 8][tx] = x[((size_t)b * C_CH + c0 + ty + k * 8) * N_SP + n0 + tx];
        __syncthreads();
#pragma unroll
        for (int k = 0; k < 4; k++) {
            int n = ty + k * 8;
            float v = tile[tx][n];
            __half h = __float2half_rn(v);
            size_t a = ((size_t)b * N_SP + n0 + n) * C_CH + c0 + tx;
            g_xth[a] = h;
            g_xtl[a] = __float2half_rn(v - __half2float(h));
        }
    } else {
        int i = (bid - 8192) * 256 + threadIdx.x;
        const float* src; __half *dh, *dl; int off;
        if (i < 32768)        { src = wq; dh = g_wqh; dl = g_wql; off = i; }
        else if (i < 65536)   { src = wk; dh = g_wkh; dl = g_wkl; off = i - 32768; }
        else                  { src = wv; dh = g_wvh; dl = g_wvl; off = i - 65536; }
        float v = src[off];
        __half h = __float2half_rn(v);
        dh[off] = h;
        dl[off] = __float2half_rn(v - __half2float(h));
    }
}

// ---------------------------------------------------------------------------
// projqk: q/k[n][64] = x^T @ W^T + bias (3-term hi/lo HMMA)
// ---------------------------------------------------------------------------
__global__ __launch_bounds__(256) void projqk_kernel(
    const float* __restrict__ bq, const float* __restrict__ bk)
{
    extern __shared__ char smx[];
    u32 sb = s2u(smx);
    int t = threadIdx.x, wid = t >> 5, l = t & 31;
    int n0 = blockIdx.x * 128, which = blockIdx.y, b = blockIdx.z;

    const char* xh = (const char*)(g_xth + ((size_t)b * N_SP + n0) * C_CH);
    const char* xl = (const char*)(g_xtl + ((size_t)b * N_SP + n0) * C_CH);
    const char* wh = (const char*)(which ? g_wkh : g_wqh);
    const char* wl = (const char*)(which ? g_wkl : g_wql);
    const float* bias = which ? bk : bq;
    __half* oh = (which ? g_kh : g_qh) + ((size_t)b * N_SP + n0) * 64;
    __half* ol = (which ? g_kl : g_ql) + ((size_t)b * N_SP + n0) * 64;

    auto load = [&](int kc, int s) {
        u32 base = s * 49152;
#pragma unroll
        for (int k2 = 0; k2 < 4; k2++) {
            int z = t + k2 * 256, r = z >> 3, c = z & 7;
            u32 off = sw128(r * 128 + c * 16);
            size_t go = (size_t)r * 1024 + kc * 128 + c * 16;
            cp16(sb + base + off, xh + go);
            cp16(sb + base + 16384 + off, xl + go);
        }
#pragma unroll
        for (int k2 = 0; k2 < 2; k2++) {
            int z = t + k2 * 256, r = z >> 3, c = z & 7;
            u32 off = sw128(r * 128 + c * 16);
            size_t go = (size_t)r * 1024 + kc * 128 + c * 16;
            cp16(sb + base + 32768 + off, wh + go);
            cp16(sb + base + 40960 + off, wl + go);
        }
        cp_commit();
    };

    int wn = wid & 3, wm = wid >> 2;
    float acc[2][4][4];
#pragma unroll
    for (int i = 0; i < 2; i++)
#pragma unroll
        for (int j = 0; j < 4; j++)
#pragma unroll
            for (int p = 0; p < 4; p++) acc[i][j][p] = 0.f;

    load(0, 0);
    for (int kc = 0; kc < 8; kc++) {
        int s = kc & 1;
        if (kc + 1 < 8) { load(kc + 1, s ^ 1); cp_wait1(); }
        else cp_wait0();
        __syncthreads();
        u32 xb0 = sb + s * 49152, wb0 = xb0 + 32768;
#pragma unroll
        for (int ks = 0; ks < 4; ks++) {
            u32 ah[2][4], al[2][4], bh[4][2], bl[4][2];
#pragma unroll
            for (int ifr = 0; ifr < 2; ifr++) {
                u32 ro = (wn * 32 + ifr * 16 + (l & 15)) * 128 + ks * 32 + ((l >> 4) & 1) * 16;
                ldsm4(ah[ifr][0], ah[ifr][1], ah[ifr][2], ah[ifr][3], xb0 + sw128(ro));
                ldsm4(al[ifr][0], al[ifr][1], al[ifr][2], al[ifr][3], xb0 + 16384 + sw128(ro));
            }
#pragma unroll
            for (int jfr = 0; jfr < 4; jfr++) {
                u32 ro = (wm * 32 + jfr * 8 + (l & 7)) * 128 + ks * 32 + ((l >> 3) & 1) * 16;
                ldsm2(bh[jfr][0], bh[jfr][1], wb0 + sw128(ro));
                ldsm2(bl[jfr][0], bl[jfr][1], wb0 + 8192 + sw128(ro));
            }
#pragma unroll
            for (int ifr = 0; ifr < 2; ifr++)
#pragma unroll
                for (int jfr = 0; jfr < 4; jfr++) {
                    mma16816(acc[ifr][jfr], ah[ifr], bh[jfr]);
                    mma16816(acc[ifr][jfr], ah[ifr], bl[jfr]);
                    mma16816(acc[ifr][jfr], al[ifr], bh[jfr]);
                }
        }
        __syncthreads();
    }

    int g = l >> 2, t4 = l & 3;
#pragma unroll
    for (int ifr = 0; ifr < 2; ifr++) {
        int r0 = wn * 32 + ifr * 16 + g;
#pragma unroll
        for (int jfr = 0; jfr < 4; jfr++) {
            int m = wm * 32 + jfr * 8 + t4 * 2;
            float bv0 = bias[m], bv1 = bias[m + 1];
            st_hl2(oh, ol, (size_t)r0 * 64 + m,
                   acc[ifr][jfr][0] + bv0, acc[ifr][jfr][1] + bv1);
            st_hl2(oh, ol, (size_t)(r0 + 8) * 64 + m,
                   acc[ifr][jfr][2] + bv0, acc[ifr][jfr][3] + bv1);
        }
    }
}

// ---------------------------------------------------------------------------
// projv: v[c][n] = Wv @ x + bias (single-term fp16 HMMA). CTA: 128c x 128n.
// ---------------------------------------------------------------------------
__global__ __launch_bounds__(256) void projv_kernel(const float* __restrict__ bv)
{
    extern __shared__ char smx[];
    u32 sb = s2u(smx);
    int t = threadIdx.x, wid = t >> 5, l = t & 31;
    int n0 = blockIdx.x * 128, c0 = blockIdx.y * 128, b = blockIdx.z;

    const char* ap = (const char*)(g_wvh + (size_t)c0 * C_CH);
    const char* bp = (const char*)(g_xth + ((size_t)b * N_SP + n0) * C_CH);
    __half* vo = g_vh + ((size_t)b * C_CH + c0) * N_SP;

    auto load = [&](int kc, int s) {
        u32 base = s * 32768;
#pragma unroll
        for (int k2 = 0; k2 < 4; k2++) {
            int z = t + k2 * 256, r = z >> 3, c = z & 7;
            u32 off = sw128(r * 128 + c * 16);
            size_t go = (size_t)r * 1024 + kc * 128 + c * 16;
            cp16(sb + base + off, ap + go);
            cp16(sb + base + 16384 + off, bp + go);
        }
        cp_commit();
    };

    int wi = wid & 1, wj = wid >> 1;
    float acc[4][4][4];
#pragma unroll
    for (int i = 0; i < 4; i++)
#pragma unroll
        for (int j = 0; j < 4; j++)
#pragma unroll
            for (int p = 0; p < 4; p++) acc[i][j][p] = 0.f;

    load(0, 0);
    for (int kc = 0; kc < 8; kc++) {
        int s = kc & 1;
        if (kc + 1 < 8) { load(kc + 1, s ^ 1); cp_wait1(); }
        else cp_wait0();
        __syncthreads();
        u32 ab0 = sb + s * 32768, bb0 = ab0 + 16384;
#pragma unroll
        for (int ks = 0; ks < 4; ks++) {
            u32 af[4][4], bf[4][2];
#pragma unroll
            for (int ifr = 0; ifr < 4; ifr++) {
                u32 ro = (wi * 64 + ifr * 16 + (l & 15)) * 128 + ks * 32 + ((l >> 4) & 1) * 16;
                ldsm4(af[ifr][0], af[ifr][1], af[ifr][2], af[ifr][3], ab0 + sw128(ro));
            }
#pragma unroll
            for (int jfr = 0; jfr < 4; jfr++) {
                u32 ro = (wj * 32 + jfr * 8 + (l & 7)) * 128 + ks * 32 + ((l >> 3) & 1) * 16;
                ldsm2(bf[jfr][0], bf[jfr][1], bb0 + sw128(ro));
            }
#pragma unroll
            for (int ifr = 0; ifr < 4; ifr++)
#pragma unroll
                for (int jfr = 0; jfr < 4; jfr++)
                    mma16816(acc[ifr][jfr], af[ifr], bf[jfr]);
        }
        __syncthreads();
    }

    int g = l >> 2, t4 = l & 3;
#pragma unroll
    for (int ifr = 0; ifr < 4; ifr++) {
        int cl = wi * 64 + ifr * 16 + g;
        float b0 = bv[c0 + cl], b1 = bv[c0 + cl + 8];
#pragma unroll
        for (int jfr = 0; jfr < 4; jfr++) {
            int nl = n0 + wj * 32 + jfr * 8 + t4 * 2;
            *(__half2*)(vo + (size_t)cl * N_SP + nl) =
                __halves2half2(__float2half_rn(acc[ifr][jfr][0] + b0),
                               __float2half_rn(acc[ifr][jfr][1] + b0));
            *(__half2*)(vo + (size_t)(cl + 8) * N_SP + nl) =
                __halves2half2(__float2half_rn(acc[ifr][jfr][2] + b1),
                               __float2half_rn(acc[ifr][jfr][3] + b1));
        }
    }
}

// ---------------------------------------------------------------------------
// S-GEMM (per batch): S = q.k^T via 3-term hi/lo HMMA. CTA: 128i x 128j.
// Split prologue: (QH,KH) in group 0, (QL,KL) in group 1; term 0 overlaps
// the second group's arrival.
// ---------------------------------------------------------------------------
__global__ __launch_bounds__(256, 2) void sgemm_kernel(int b)
{
    extern __shared__ char smx[];
    const u32 QH = 0, QL = 16384, KH = 32768, KL = 49152;
    u32 sb = s2u(smx);
    int t = threadIdx.x, wid = t >> 5, l = t & 31;
    int j0 = blockIdx.x * 128, i0 = blockIdx.y * 128;

    const char* qhp = (const char*)(g_qh + ((size_t)b * N_SP + i0) * 64);
    const char* qlp = (const char*)(g_ql + ((size_t)b * N_SP + i0) * 64);
    const char* khp = (const char*)(g_kh + ((size_t)b * N_SP + j0) * 64);
    const char* klp = (const char*)(g_kl + ((size_t)b * N_SP + j0) * 64);

#pragma unroll
    for (int it = 0; it < 4; it++) {            // group 0: QH + KH
        int z = t + it * 256, r = z >> 3, c = z & 7;
        u32 off = sw128(r * 128 + c * 16);
        int go = r * 128 + c * 16;
        cp16(sb + QH + off, qhp + go);
        cp16(sb + KH + off, khp + go);
    }
    cp_commit();
#pragma unroll
    for (int it = 0; it < 4; it++) {            // group 1: QL + KL
        int z = t + it * 256, r = z >> 3, c = z & 7;
        u32 off = sw128(r * 128 + c * 16);
        int go = r * 128 + c * 16;
        cp16(sb + QL + off, qlp + go);
        cp16(sb + KL + off, klp + go);
    }
    cp_commit();

    int wi = wid & 1, wj = wid >> 1;
    int g = l >> 2, t4 = l & 3;

    float acc[4][4][4];
#pragma unroll
    for (int i = 0; i < 4; i++)
#pragma unroll
        for (int j = 0; j < 4; j++)
#pragma unroll
            for (int p = 0; p < 4; p++) acc[i][j][p] = 0.f;

    const u32 ab[3] = { QH, QH, QL };
    const u32 bb[3] = { KH, KL, KH };

    cp_wait1();                                  // group 0 (QH,KH) resident
    __syncthreads();

#pragma unroll
    for (int term = 0; term < 3; term++) {
        if (term == 1) {                         // need QL/KL from here on
            cp_wait0();
            __syncthreads();
        }
#pragma unroll
        for (int ks = 0; ks < 4; ks++) {
            u32 af[4][4], bf[4][2];
#pragma unroll
            for (int ifr = 0; ifr < 4; ifr++) {
                u32 a = sb + ab[term] + sw128((wi * 64 + ifr * 16 + (l & 15)) * 128
                                              + ks * 32 + ((l >> 4) & 1) * 16);
                ldsm4(af[ifr][0], af[ifr][1], af[ifr][2], af[ifr][3], a);
            }
#pragma unroll
            for (int jfr = 0; jfr < 4; jfr++) {
                u32 a = sb + bb[term] + sw128((wj * 32 + jfr * 8 + (l & 7)) * 128
                                              + ks * 32 + ((l >> 3) & 1) * 16);
                ldsm2(bf[jfr][0], bf[jfr][1], a);
            }
#pragma unroll
            for (int ifr = 0; ifr < 4; ifr++)
#pragma unroll
                for (int jfr = 0; jfr < 4; jfr++)
                    mma16816(acc[ifr][jfr], af[ifr], bf[jfr]);
        }
    }

    float* S = g_S + (size_t)b * N_SP * N_SP;
#pragma unroll
    for (int ifr = 0; ifr < 4; ifr++) {
        int r0 = i0 + wi * 64 + ifr * 16 + g;
#pragma unroll
        for (int jfr = 0; jfr < 4; jfr++) {
            int col = j0 + wj * 32 + jfr * 8 + t4 * 2;
            float2 d0 = { acc[ifr][jfr][0], acc[ifr][jfr][1] };
            float2 d1 = { acc[ifr][jfr][2], acc[ifr][jfr][3] };
            *(float2*)&S[(size_t)r0 * N_SP + col]       = d0;
            *(float2*)&S[(size_t)(r0 + 8) * N_SP + col] = d1;
        }
    }
}

// ---------------------------------------------------------------------------
// Softmax (per batch): one row per block.
// ---------------------------------------------------------------------------
__global__ __launch_bounds__(256) void softmax_kernel(int b)
{
    __shared__ float red[8];
    int i = blockIdx.x, t = threadIdx.x, wid = t >> 5;
    const float* S = g_S + ((size_t)b * N_SP + i) * N_SP;
    __half* P = g_P + ((size_t)b * N_SP + i) * N_SP;

    float4 v[4];
    float mx = -1e30f;
#pragma unroll
    for (int k = 0; k < 4; k++) {
        v[k] = *(const float4*)&S[(k * 256 + t) * 4];
        mx = fmaxf(mx, fmaxf(fmaxf(v[k].x, v[k].y), fmaxf(v[k].z, v[k].w)));
    }
#pragma unroll
    for (int w = 1; w < 32; w <<= 1) mx = fmaxf(mx, __shfl_xor_sync(~0u, mx, w));
    if ((t & 31) == 0) red[wid] = mx;
    __syncthreads();
    mx = red[0];
#pragma unroll
    for (int w = 1; w < 8; w++) mx = fmaxf(mx, red[w]);
    __syncthreads();

    float sum = 0.f;
#pragma unroll
    for (int k = 0; k < 4; k++) {
        __half h0 = __float2half_rn(__expf(v[k].x - mx));
        __half h1 = __float2half_rn(__expf(v[k].y - mx));
        __half h2 = __float2half_rn(__expf(v[k].z - mx));
        __half h3 = __float2half_rn(__expf(v[k].w - mx));
        sum += __half2float(h0) + __half2float(h1) + __half2float(h2) + __half2float(h3);
        *(__half2*)&P[(k * 256 + t) * 4]     = __halves2half2(h0, h1);
        *(__half2*)&P[(k * 256 + t) * 4 + 2] = __halves2half2(h2, h3);
    }
#pragma unroll
    for (int w = 1; w < 32; w <<= 1) sum += __shfl_xor_sync(~0u, sum, w);
    if ((t & 31) == 0) red[wid] = sum;
    __syncthreads();
    if (t == 0) {
        float s = 0.f;
#pragma unroll
        for (int w = 0; w < 8; w++) s += red[w];
        g_l[(size_t)b * N_SP + i] = s;
    }
}

// ---------------------------------------------------------------------------
// PV (per batch): feat = P.V^T. CTA: 128i x 128c, 3-stage pipeline.
// ---------------------------------------------------------------------------
__global__ __launch_bounds__(256, 2) void pv_kernel(
    const float* __restrict__ xin, const float* __restrict__ gamma,
    float* __restrict__ out, int b)
{
    extern __shared__ char smx[];
    u32 sb = s2u(smx);
    int t = threadIdx.x, wid = t >> 5, l = t & 31;
    int c0 = blockIdx.x * 128, i0 = blockIdx.y * 128;

    const char* pp = (const char*)(g_P  + ((size_t)b * N_SP + i0) * N_SP);
    const char* vp = (const char*)(g_vh + ((size_t)b * C_CH + c0) * N_SP);

    auto load_chunk = [&](int jc) {
        int s = jc % 3;
        size_t jb = (size_t)jc * 128;
        u32 base = (u32)s * 32768;
#pragma unroll
        for (int it = 0; it < 4; it++) {
            int z = t + it * 256, r = z >> 3, c = z & 7;
            u32 off = sw128(r * 128 + c * 16);
            cp16(sb + base + off, pp + (size_t)r * 8192 + jb + c * 16);
            cp16(sb + base + 16384 + off, vp + (size_t)r * 8192 + jb + c * 16);
        }
        cp_commit();
    };

    int wi = wid & 1, wc = wid >> 1;
    int g = l >> 2, t4 = l & 3;
    int grp = l >> 3;
    int bhalf = grp & 1;
    int bsub  = grp >> 1;

    float acc[4][4][4];
#pragma unroll
    for (int i = 0; i < 4; i++)
#pragma unroll
        for (int j = 0; j < 4; j++)
#pragma unroll
            for (int p = 0; p < 4; p++) acc[i][j][p] = 0.f;

    load_chunk(0);
    load_chunk(1);
    for (int it = 0; it < 64; it++) {
        if (it + 1 < 64) cp_wait1(); else cp_wait0();
        __syncthreads();
        if (it + 2 < 64) load_chunk(it + 2);
        u32 base = sb + (u32)(it % 3) * 32768;
#pragma unroll
        for (int ks = 0; ks < 4; ks++) {
            u32 af[4][4], bf[4][2];
#pragma unroll
            for (int ifr = 0; ifr < 4; ifr++) {
                u32 a = base + sw128((wi * 64 + ifr * 16 + (l & 15)) * 128
                                     + ks * 32 + ((l >> 4) & 1) * 16);
                ldsm4(af[ifr][0], af[ifr][1], af[ifr][2], af[ifr][3], a);
            }
#pragma unroll
            for (int cp2 = 0; cp2 < 2; cp2++) {
                int cfr = cp2 * 2 + bsub;
                u32 a = base + 16384 + sw128((wc * 32 + cfr * 8 + (l & 7)) * 128
                                             + ks * 32 + bhalf * 16);
                ldsm4(bf[cp2 * 2][0], bf[cp2 * 2][1],
                      bf[cp2 * 2 + 1][0], bf[cp2 * 2 + 1][1], a);
            }
#pragma unroll
            for (int ifr = 0; ifr < 4; ifr++)
#pragma unroll
                for (int cfr = 0; cfr < 4; cfr++)
                    mma16816(acc[ifr][cfr], af[ifr], bf[cfr]);
        }
    }

    float gam = gamma[0];
    float linv[4][2];
#pragma unroll
    for (int ifr = 0; ifr < 4; ifr++) {
        int i = i0 + wi * 64 + ifr * 16 + g;
        linv[ifr][0] = gam / g_l[(size_t)b * N_SP + i];
        linv[ifr][1] = gam / g_l[(size_t)b * N_SP + i + 8];
    }
#pragma unroll
    for (int ifr = 0; ifr < 4; ifr++) {
        int i = i0 + wi * 64 + ifr * 16 + g;
#pragma unroll
        for (int cfr = 0; cfr < 4; cfr++) {
            int c = c0 + wc * 32 + cfr * 8 + t4 * 2;
            size_t base = ((size_t)b * C_CH + c) * N_SP;
            out[base + i]            = acc[ifr][cfr][0] * linv[ifr][0] + xin[base + i];
            out[base + N_SP + i]     = acc[ifr][cfr][1] * linv[ifr][0] + xin[base + N_SP + i];
            out[base + i + 8]        = acc[ifr][cfr][2] * linv[ifr][1] + xin[base + i + 8];
            out[base + N_SP + i + 8] = acc[ifr][cfr][3] * linv[ifr][1] + xin[base + N_SP + i + 8];
        }
    }
}

// ---------------------------------------------------------------------------
extern "C" void kernel_launch(void* const* d_in, const int* in_sizes, int n_in,
                              void* d_out, int out_size)
{
    const float* x  = (const float*)d_in[0];
    const float* Wq = (const float*)d_in[1];
    const float* bq = (const float*)d_in[2];
    const float* Wk = (const float*)d_in[3];
    const float* bk = (const float*)d_in[4];
    const float* Wv = (const float*)d_in[5];
    const float* bv = (const float*)d_in[6];
    const float* gm = (const float*)d_in[7];
    float* out = (float*)d_out;

    static cudaStream_t s1 = nullptr, s2 = nullptr, s3 = nullptr;
    static cudaEvent_t evFork = nullptr, evPV = nullptr, evEnd1 = nullptr, evEnd2 = nullptr;
    static cudaEvent_t evS[4], evM[4];
    if (!s1) {
        cudaStreamCreateWithFlags(&s1, cudaStreamNonBlocking);
        cudaStreamCreateWithFlags(&s2, cudaStreamNonBlocking);
        cudaStreamCreateWithFlags(&s3, cudaStreamNonBlocking);
        cudaEventCreateWithFlags(&evFork, cudaEventDisableTiming);
        cudaEventCreateWithFlags(&evPV, cudaEventDisableTiming);
        cudaEventCreateWithFlags(&evEnd1, cudaEventDisableTiming);
        cudaEventCreateWithFlags(&evEnd2, cudaEventDisableTiming);
        for (int b = 0; b < 4; b++) {
            cudaEventCreateWithFlags(&evS[b], cudaEventDisableTiming);
            cudaEventCreateWithFlags(&evM[b], cudaEventDisableTiming);
        }
        cudaFuncSetAttribute(projqk_kernel, cudaFuncAttributeMaxDynamicSharedMemorySize, 98304);
        cudaFuncSetAttribute(projv_kernel,  cudaFuncAttributeMaxDynamicSharedMemorySize, 65536);
        cudaFuncSetAttribute(sgemm_kernel,  cudaFuncAttributeMaxDynamicSharedMemorySize, 65536);
        cudaFuncSetAttribute(pv_kernel,     cudaFuncAttributeMaxDynamicSharedMemorySize, 98304);
    }

    conv_kernel<<<9472, 256>>>(x, Wq, Wk, Wv);
    cudaEventRecord(evFork, 0);

    // s1: projv (only needed by pv), later reused for pv batches 1,3
    cudaStreamWaitEvent(s1, evFork, 0);
    projv_kernel<<<dim3(32, 4, 4), 256, 65536, s1>>>(bv);
    cudaEventRecord(evPV, s1);

    // main: projqk then per-batch sgemm; softmax per batch chases on s2
    projqk_kernel<<<dim3(32, 2, 4), 256, 98304>>>(bq, bk);
    for (int b = 0; b < 4; b++) {
        sgemm_kernel<<<dim3(32, 32), 256, 65536>>>(b);
        cudaEventRecord(evS[b], 0);
        cudaStreamWaitEvent(s2, evS[b], 0);
        softmax_kernel<<<4096, 256, 0, s2>>>(b);
        cudaEventRecord(evM[b], s2);
    }

    // pv per batch, earliest start, alternating s3 (even) / s1 (odd)
    cudaStreamWaitEvent(s3, evPV, 0);
    cudaStreamWaitEvent(s3, evM[0], 0);
    pv_kernel<<<dim3(4, 32), 256, 98304, s3>>>(x, gm, out, 0);
    cudaStreamWaitEvent(s1, evM[1], 0);
    pv_kernel<<<dim3(4, 32), 256, 98304, s1>>>(x, gm, out, 1);
    cudaStreamWaitEvent(s3, evM[2], 0);
    pv_kernel<<<dim3(4, 32), 256, 98304, s3>>>(x, gm, out, 2);
    cudaStreamWaitEvent(s1, evM[3], 0);
    pv_kernel<<<dim3(4, 32), 256, 98304, s1>>>(x, gm, out, 3);
    cudaEventRecord(evEnd1, s3);
    cudaEventRecord(evEnd2, s1);

    cudaStreamWaitEvent(0, evEnd1, 0);
    cudaStreamWaitEvent(0, evEnd2, 0);
}

// round 16
// speedup vs baseline: 1.0324x; 1.0324x over previous
#include <cuda_runtime.h>
#include <cuda_fp16.h>
#include <cstdint>

#define N_SP 4096
#define C_CH 512
#define B_SZ 4

typedef unsigned long long u64;
typedef unsigned int u32;

__device__ __half g_xth[(size_t)B_SZ * N_SP * C_CH];
__device__ __half g_xtl[(size_t)B_SZ * N_SP * C_CH];
__device__ __half g_wqh[64 * C_CH], g_wql[64 * C_CH];
__device__ __half g_wkh[64 * C_CH], g_wkl[64 * C_CH];
__device__ __half g_wvh[C_CH * C_CH], g_wvl[C_CH * C_CH];
__device__ __half g_qh[(size_t)B_SZ * N_SP * 64];
__device__ __half g_ql[(size_t)B_SZ * N_SP * 64];
__device__ __half g_kh[(size_t)B_SZ * N_SP * 64];
__device__ __half g_kl[(size_t)B_SZ * N_SP * 64];
__device__ __half g_vh[(size_t)B_SZ * C_CH * N_SP];
__device__ float  g_S [(size_t)B_SZ * N_SP * N_SP];
__device__ __half g_P [(size_t)B_SZ * N_SP * N_SP];
__device__ float  g_l [(size_t)B_SZ * N_SP];

__device__ __forceinline__ u32 s2u(const void* p) { return (u32)__cvta_generic_to_shared(p); }
__device__ __forceinline__ void cp16(u32 d, const void* s) {
    asm volatile("cp.async.cg.shared.global [%0], [%1], 16;" :: "r"(d), "l"(s));
}
__device__ __forceinline__ void cp_commit() { asm volatile("cp.async.commit_group;"); }
__device__ __forceinline__ void cp_wait0()  { asm volatile("cp.async.wait_group 0;"); }
__device__ __forceinline__ void cp_wait1()  { asm volatile("cp.async.wait_group 1;"); }
__device__ __forceinline__ u32 sw128(u32 o) { return o ^ ((o >> 3) & 0x70); }

__device__ __forceinline__ void ldsm4(u32& r0, u32& r1, u32& r2, u32& r3, u32 a) {
    asm volatile("ldmatrix.sync.aligned.m8n8.x4.shared.b16 {%0,%1,%2,%3}, [%4];"
                 : "=r"(r0), "=r"(r1), "=r"(r2), "=r"(r3) : "r"(a));
}
__device__ __forceinline__ void ldsm2(u32& r0, u32& r1, u32 a) {
    asm volatile("ldmatrix.sync.aligned.m8n8.x2.shared.b16 {%0,%1}, [%2];"
                 : "=r"(r0), "=r"(r1) : "r"(a));
}
__device__ __forceinline__ void mma16816(float* d, const u32* a, const u32* b) {
    asm volatile("mma.sync.aligned.m16n8k16.row.col.f32.f16.f16.f32 "
                 "{%0,%1,%2,%3}, {%4,%5,%6,%7}, {%8,%9}, {%0,%1,%2,%3};"
                 : "+f"(d[0]), "+f"(d[1]), "+f"(d[2]), "+f"(d[3])
                 : "r"(a[0]), "r"(a[1]), "r"(a[2]), "r"(a[3]), "r"(b[0]), "r"(b[1]));
}
__device__ __forceinline__ void st_hl2(__half* ph, __half* pl, size_t a, float o0, float o1) {
    __half h0 = __float2half_rn(o0), h1 = __float2half_rn(o1);
    __half l0 = __float2half_rn(o0 - __half2float(h0));
    __half l1 = __float2half_rn(o1 - __half2float(h1));
    *(__half2*)(ph + a) = __halves2half2(h0, h1);
    *(__half2*)(pl + a) = __halves2half2(l0, l1);
}

// ---------------------------------------------------------------------------
// conv (merged): blocks 0..8191 transpose+split x; 8192..9471 split weights
// ---------------------------------------------------------------------------
__global__ __launch_bounds__(256) void conv_kernel(
    const float* __restrict__ x, const float* __restrict__ wq,
    const float* __restrict__ wk, const float* __restrict__ wv)
{
    __shared__ float tile[32][33];
    int bid = blockIdx.x;
    if (bid < 8192) {
        int tx = threadIdx.x & 31, ty = threadIdx.x >> 5;
        int n0 = (bid & 127) * 32, c0 = ((bid >> 7) & 15) * 32, b = bid >> 11;
#pragma unroll
        for (int k = 0; k < 4; k++)
            tile[ty + k * 8][tx] = x[((size_t)b * C_CH + c0 + ty + k * 8) * N_SP + n0 + tx];
        __syncthreads();
#pragma unroll
        for (int k = 0; k < 4; k++) {
            int n = ty + k * 8;
            float v = tile[tx][n];
            __half h = __float2half_rn(v);
            size_t a = ((size_t)b * N_SP + n0 + n) * C_CH + c0 + tx;
            g_xth[a] = h;
            g_xtl[a] = __float2half_rn(v - __half2float(h));
        }
    } else {
        int i = (bid - 8192) * 256 + threadIdx.x;
        const float* src; __half *dh, *dl; int off;
        if (i < 32768)        { src = wq; dh = g_wqh; dl = g_wql; off = i; }
        else if (i < 65536)   { src = wk; dh = g_wkh; dl = g_wkl; off = i - 32768; }
        else                  { src = wv; dh = g_wvh; dl = g_wvl; off = i - 65536; }
        float v = src[off];
        __half h = __float2half_rn(v);
        dh[off] = h;
        dl[off] = __float2half_rn(v - __half2float(h));
    }
}

// ---------------------------------------------------------------------------
// projqk: q/k[n][64] = x^T @ W^T + bias (3-term hi/lo HMMA)
// ---------------------------------------------------------------------------
__global__ __launch_bounds__(256) void projqk_kernel(
    const float* __restrict__ bq, const float* __restrict__ bk)
{
    extern __shared__ char smx[];
    u32 sb = s2u(smx);
    int t = threadIdx.x, wid = t >> 5, l = t & 31;
    int n0 = blockIdx.x * 128, which = blockIdx.y, b = blockIdx.z;

    const char* xh = (const char*)(g_xth + ((size_t)b * N_SP + n0) * C_CH);
    const char* xl = (const char*)(g_xtl + ((size_t)b * N_SP + n0) * C_CH);
    const char* wh = (const char*)(which ? g_wkh : g_wqh);
    const char* wl = (const char*)(which ? g_wkl : g_wql);
    const float* bias = which ? bk : bq;
    __half* oh = (which ? g_kh : g_qh) + ((size_t)b * N_SP + n0) * 64;
    __half* ol = (which ? g_kl : g_ql) + ((size_t)b * N_SP + n0) * 64;

    auto load = [&](int kc, int s) {
        u32 base = s * 49152;
#pragma unroll
        for (int k2 = 0; k2 < 4; k2++) {
            int z = t + k2 * 256, r = z >> 3, c = z & 7;
            u32 off = sw128(r * 128 + c * 16);
            size_t go = (size_t)r * 1024 + kc * 128 + c * 16;
            cp16(sb + base + off, xh + go);
            cp16(sb + base + 16384 + off, xl + go);
        }
#pragma unroll
        for (int k2 = 0; k2 < 2; k2++) {
            int z = t + k2 * 256, r = z >> 3, c = z & 7;
            u32 off = sw128(r * 128 + c * 16);
            size_t go = (size_t)r * 1024 + kc * 128 + c * 16;
            cp16(sb + base + 32768 + off, wh + go);
            cp16(sb + base + 40960 + off, wl + go);
        }
        cp_commit();
    };

    int wn = wid & 3, wm = wid >> 2;
    float acc[2][4][4];
#pragma unroll
    for (int i = 0; i < 2; i++)
#pragma unroll
        for (int j = 0; j < 4; j++)
#pragma unroll
            for (int p = 0; p < 4; p++) acc[i][j][p] = 0.f;

    load(0, 0);
    for (int kc = 0; kc < 8; kc++) {
        int s = kc & 1;
        if (kc + 1 < 8) { load(kc + 1, s ^ 1); cp_wait1(); }
        else cp_wait0();
        __syncthreads();
        u32 xb0 = sb + s * 49152, wb0 = xb0 + 32768;
#pragma unroll
        for (int ks = 0; ks < 4; ks++) {
            u32 ah[2][4], al[2][4], bh[4][2], bl[4][2];
#pragma unroll
            for (int ifr = 0; ifr < 2; ifr++) {
                u32 ro = (wn * 32 + ifr * 16 + (l & 15)) * 128 + ks * 32 + ((l >> 4) & 1) * 16;
                ldsm4(ah[ifr][0], ah[ifr][1], ah[ifr][2], ah[ifr][3], xb0 + sw128(ro));
                ldsm4(al[ifr][0], al[ifr][1], al[ifr][2], al[ifr][3], xb0 + 16384 + sw128(ro));
            }
#pragma unroll
            for (int jfr = 0; jfr < 4; jfr++) {
                u32 ro = (wm * 32 + jfr * 8 + (l & 7)) * 128 + ks * 32 + ((l >> 3) & 1) * 16;
                ldsm2(bh[jfr][0], bh[jfr][1], wb0 + sw128(ro));
                ldsm2(bl[jfr][0], bl[jfr][1], wb0 + 8192 + sw128(ro));
            }
#pragma unroll
            for (int ifr = 0; ifr < 2; ifr++)
#pragma unroll
                for (int jfr = 0; jfr < 4; jfr++) {
                    mma16816(acc[ifr][jfr], ah[ifr], bh[jfr]);
                    mma16816(acc[ifr][jfr], ah[ifr], bl[jfr]);
                    mma16816(acc[ifr][jfr], al[ifr], bh[jfr]);
                }
        }
        __syncthreads();
    }

    int g = l >> 2, t4 = l & 3;
#pragma unroll
    for (int ifr = 0; ifr < 2; ifr++) {
        int r0 = wn * 32 + ifr * 16 + g;
#pragma unroll
        for (int jfr = 0; jfr < 4; jfr++) {
            int m = wm * 32 + jfr * 8 + t4 * 2;
            float bv0 = bias[m], bv1 = bias[m + 1];
            st_hl2(oh, ol, (size_t)r0 * 64 + m,
                   acc[ifr][jfr][0] + bv0, acc[ifr][jfr][1] + bv1);
            st_hl2(oh, ol, (size_t)(r0 + 8) * 64 + m,
                   acc[ifr][jfr][2] + bv0, acc[ifr][jfr][3] + bv1);
        }
    }
}

// ---------------------------------------------------------------------------
// projv: v[c][n] = Wv @ x + bias (single-term fp16 HMMA). CTA: 128c x 128n.
// ---------------------------------------------------------------------------
__global__ __launch_bounds__(256) void projv_kernel(const float* __restrict__ bv)
{
    extern __shared__ char smx[];
    u32 sb = s2u(smx);
    int t = threadIdx.x, wid = t >> 5, l = t & 31;
    int n0 = blockIdx.x * 128, c0 = blockIdx.y * 128, b = blockIdx.z;

    const char* ap = (const char*)(g_wvh + (size_t)c0 * C_CH);
    const char* bp = (const char*)(g_xth + ((size_t)b * N_SP + n0) * C_CH);
    __half* vo = g_vh + ((size_t)b * C_CH + c0) * N_SP;

    auto load = [&](int kc, int s) {
        u32 base = s * 32768;
#pragma unroll
        for (int k2 = 0; k2 < 4; k2++) {
            int z = t + k2 * 256, r = z >> 3, c = z & 7;
            u32 off = sw128(r * 128 + c * 16);
            size_t go = (size_t)r * 1024 + kc * 128 + c * 16;
            cp16(sb + base + off, ap + go);
            cp16(sb + base + 16384 + off, bp + go);
        }
        cp_commit();
    };

    int wi = wid & 1, wj = wid >> 1;
    float acc[4][4][4];
#pragma unroll
    for (int i = 0; i < 4; i++)
#pragma unroll
        for (int j = 0; j < 4; j++)
#pragma unroll
            for (int p = 0; p < 4; p++) acc[i][j][p] = 0.f;

    load(0, 0);
    for (int kc = 0; kc < 8; kc++) {
        int s = kc & 1;
        if (kc + 1 < 8) { load(kc + 1, s ^ 1); cp_wait1(); }
        else cp_wait0();
        __syncthreads();
        u32 ab0 = sb + s * 32768, bb0 = ab0 + 16384;
#pragma unroll
        for (int ks = 0; ks < 4; ks++) {
            u32 af[4][4], bf[4][2];
#pragma unroll
            for (int ifr = 0; ifr < 4; ifr++) {
                u32 ro = (wi * 64 + ifr * 16 + (l & 15)) * 128 + ks * 32 + ((l >> 4) & 1) * 16;
                ldsm4(af[ifr][0], af[ifr][1], af[ifr][2], af[ifr][3], ab0 + sw128(ro));
            }
#pragma unroll
            for (int jfr = 0; jfr < 4; jfr++) {
                u32 ro = (wj * 32 + jfr * 8 + (l & 7)) * 128 + ks * 32 + ((l >> 3) & 1) * 16;
                ldsm2(bf[jfr][0], bf[jfr][1], bb0 + sw128(ro));
            }
#pragma unroll
            for (int ifr = 0; ifr < 4; ifr++)
#pragma unroll
                for (int jfr = 0; jfr < 4; jfr++)
                    mma16816(acc[ifr][jfr], af[ifr], bf[jfr]);
        }
        __syncthreads();
    }

    int g = l >> 2, t4 = l & 3;
#pragma unroll
    for (int ifr = 0; ifr < 4; ifr++) {
        int cl = wi * 64 + ifr * 16 + g;
        float b0 = bv[c0 + cl], b1 = bv[c0 + cl + 8];
#pragma unroll
        for (int jfr = 0; jfr < 4; jfr++) {
            int nl = n0 + wj * 32 + jfr * 8 + t4 * 2;
            *(__half2*)(vo + (size_t)cl * N_SP + nl) =
                __halves2half2(__float2half_rn(acc[ifr][jfr][0] + b0),
                               __float2half_rn(acc[ifr][jfr][1] + b0));
            *(__half2*)(vo + (size_t)(cl + 8) * N_SP + nl) =
                __halves2half2(__float2half_rn(acc[ifr][jfr][2] + b1),
                               __float2half_rn(acc[ifr][jfr][3] + b1));
        }
    }
}

// ---------------------------------------------------------------------------
// S-GEMM (per batch): S = q.k^T via 3-term hi/lo HMMA. CTA: 128i x 128j.
// ---------------------------------------------------------------------------
__global__ __launch_bounds__(256, 2) void sgemm_kernel(int b)
{
    extern __shared__ char smx[];
    const u32 QH = 0, QL = 16384, KH = 32768, KL = 49152;
    u32 sb = s2u(smx);
    int t = threadIdx.x, wid = t >> 5, l = t & 31;
    int j0 = blockIdx.x * 128, i0 = blockIdx.y * 128;

    const char* qhp = (const char*)(g_qh + ((size_t)b * N_SP + i0) * 64);
    const char* qlp = (const char*)(g_ql + ((size_t)b * N_SP + i0) * 64);
    const char* khp = (const char*)(g_kh + ((size_t)b * N_SP + j0) * 64);
    const char* klp = (const char*)(g_kl + ((size_t)b * N_SP + j0) * 64);

#pragma unroll
    for (int it = 0; it < 4; it++) {
        int z = t + it * 256, r = z >> 3, c = z & 7;
        u32 off = sw128(r * 128 + c * 16);
        int go = r * 128 + c * 16;
        cp16(sb + QH + off, qhp + go);
        cp16(sb + QL + off, qlp + go);
        cp16(sb + KH + off, khp + go);
        cp16(sb + KL + off, klp + go);
    }
    cp_commit(); cp_wait0();
    __syncthreads();

    int wi = wid & 1, wj = wid >> 1;
    int g = l >> 2, t4 = l & 3;

    float acc[4][4][4];
#pragma unroll
    for (int i = 0; i < 4; i++)
#pragma unroll
        for (int j = 0; j < 4; j++)
#pragma unroll
            for (int p = 0; p < 4; p++) acc[i][j][p] = 0.f;

    const u32 ab[3] = { QH, QH, QL };
    const u32 bb[3] = { KH, KL, KH };

#pragma unroll
    for (int term = 0; term < 3; term++) {
#pragma unroll
        for (int ks = 0; ks < 4; ks++) {
            u32 af[4][4], bf[4][2];
#pragma unroll
            for (int ifr = 0; ifr < 4; ifr++) {
                u32 a = sb + ab[term] + sw128((wi * 64 + ifr * 16 + (l & 15)) * 128
                                              + ks * 32 + ((l >> 4) & 1) * 16);
                ldsm4(af[ifr][0], af[ifr][1], af[ifr][2], af[ifr][3], a);
            }
#pragma unroll
            for (int jfr = 0; jfr < 4; jfr++) {
                u32 a = sb + bb[term] + sw128((wj * 32 + jfr * 8 + (l & 7)) * 128
                                              + ks * 32 + ((l >> 3) & 1) * 16);
                ldsm2(bf[jfr][0], bf[jfr][1], a);
            }
#pragma unroll
            for (int ifr = 0; ifr < 4; ifr++)
#pragma unroll
                for (int jfr = 0; jfr < 4; jfr++)
                    mma16816(acc[ifr][jfr], af[ifr], bf[jfr]);
        }
    }

    float* S = g_S + (size_t)b * N_SP * N_SP;
#pragma unroll
    for (int ifr = 0; ifr < 4; ifr++) {
        int r0 = i0 + wi * 64 + ifr * 16 + g;
#pragma unroll
        for (int jfr = 0; jfr < 4; jfr++) {
            int col = j0 + wj * 32 + jfr * 8 + t4 * 2;
            float2 d0 = { acc[ifr][jfr][0], acc[ifr][jfr][1] };
            float2 d1 = { acc[ifr][jfr][2], acc[ifr][jfr][3] };
            *(float2*)&S[(size_t)r0 * N_SP + col]       = d0;
            *(float2*)&S[(size_t)(r0 + 8) * N_SP + col] = d1;
        }
    }
}

// ---------------------------------------------------------------------------
// Softmax (per batch): one row per block.
// ---------------------------------------------------------------------------
__global__ __launch_bounds__(256) void softmax_kernel(int b)
{
    __shared__ float red[8];
    int i = blockIdx.x, t = threadIdx.x, wid = t >> 5;
    const float* S = g_S + ((size_t)b * N_SP + i) * N_SP;
    __half* P = g_P + ((size_t)b * N_SP + i) * N_SP;

    float4 v[4];
    float mx = -1e30f;
#pragma unroll
    for (int k = 0; k < 4; k++) {
        v[k] = *(const float4*)&S[(k * 256 + t) * 4];
        mx = fmaxf(mx, fmaxf(fmaxf(v[k].x, v[k].y), fmaxf(v[k].z, v[k].w)));
    }
#pragma unroll
    for (int w = 1; w < 32; w <<= 1) mx = fmaxf(mx, __shfl_xor_sync(~0u, mx, w));
    if ((t & 31) == 0) red[wid] = mx;
    __syncthreads();
    mx = red[0];
#pragma unroll
    for (int w = 1; w < 8; w++) mx = fmaxf(mx, red[w]);
    __syncthreads();

    float sum = 0.f;
#pragma unroll
    for (int k = 0; k < 4; k++) {
        __half h0 = __float2half_rn(__expf(v[k].x - mx));
        __half h1 = __float2half_rn(__expf(v[k].y - mx));
        __half h2 = __float2half_rn(__expf(v[k].z - mx));
        __half h3 = __float2half_rn(__expf(v[k].w - mx));
        sum += __half2float(h0) + __half2float(h1) + __half2float(h2) + __half2float(h3);
        *(__half2*)&P[(k * 256 + t) * 4]     = __halves2half2(h0, h1);
        *(__half2*)&P[(k * 256 + t) * 4 + 2] = __halves2half2(h2, h3);
    }
#pragma unroll
    for (int w = 1; w < 32; w <<= 1) sum += __shfl_xor_sync(~0u, sum, w);
    if ((t & 31) == 0) red[wid] = sum;
    __syncthreads();
    if (t == 0) {
        float s = 0.f;
#pragma unroll
        for (int w = 0; w < 8; w++) s += red[w];
        g_l[(size_t)b * N_SP + i] = s;
    }
}

// ---------------------------------------------------------------------------
// PV (2 batches per launch): feat = P.V^T. CTA: 128i x 128c, 3-stage pipeline.
// ---------------------------------------------------------------------------
__global__ __launch_bounds__(256, 2) void pv_kernel(
    const float* __restrict__ xin, const float* __restrict__ gamma,
    float* __restrict__ out, int b0)
{
    extern __shared__ char smx[];
    u32 sb = s2u(smx);
    int t = threadIdx.x, wid = t >> 5, l = t & 31;
    int c0 = blockIdx.x * 128, i0 = blockIdx.y * 128, b = b0 + blockIdx.z;

    const char* pp = (const char*)(g_P  + ((size_t)b * N_SP + i0) * N_SP);
    const char* vp = (const char*)(g_vh + ((size_t)b * C_CH + c0) * N_SP);

    auto load_chunk = [&](int jc) {
        int s = jc % 3;
        size_t jb = (size_t)jc * 128;
        u32 base = (u32)s * 32768;
#pragma unroll
        for (int it = 0; it < 4; it++) {
            int z = t + it * 256, r = z >> 3, c = z & 7;
            u32 off = sw128(r * 128 + c * 16);
            cp16(sb + base + off, pp + (size_t)r * 8192 + jb + c * 16);
            cp16(sb + base + 16384 + off, vp + (size_t)r * 8192 + jb + c * 16);
        }
        cp_commit();
    };

    int wi = wid & 1, wc = wid >> 1;
    int g = l >> 2, t4 = l & 3;
    int grp = l >> 3;
    int bhalf = grp & 1;
    int bsub  = grp >> 1;

    float acc[4][4][4];
#pragma unroll
    for (int i = 0; i < 4; i++)
#pragma unroll
        for (int j = 0; j < 4; j++)
#pragma unroll
            for (int p = 0; p < 4; p++) acc[i][j][p] = 0.f;

    load_chunk(0);
    load_chunk(1);
    for (int it = 0; it < 64; it++) {
        if (it + 1 < 64) cp_wait1(); else cp_wait0();
        __syncthreads();
        if (it + 2 < 64) load_chunk(it + 2);
        u32 base = sb + (u32)(it % 3) * 32768;
#pragma unroll
        for (int ks = 0; ks < 4; ks++) {
            u32 af[4][4], bf[4][2];
#pragma unroll
            for (int ifr = 0; ifr < 4; ifr++) {
                u32 a = base + sw128((wi * 64 + ifr * 16 + (l & 15)) * 128
                                     + ks * 32 + ((l >> 4) & 1) * 16);
                ldsm4(af[ifr][0], af[ifr][1], af[ifr][2], af[ifr][3], a);
            }
#pragma unroll
            for (int cp2 = 0; cp2 < 2; cp2++) {
                int cfr = cp2 * 2 + bsub;
                u32 a = base + 16384 + sw128((wc * 32 + cfr * 8 + (l & 7)) * 128
                                             + ks * 32 + bhalf * 16);
                ldsm4(bf[cp2 * 2][0], bf[cp2 * 2][1],
                      bf[cp2 * 2 + 1][0], bf[cp2 * 2 + 1][1], a);
            }
#pragma unroll
            for (int ifr = 0; ifr < 4; ifr++)
#pragma unroll
                for (int cfr = 0; cfr < 4; cfr++)
                    mma16816(acc[ifr][cfr], af[ifr], bf[cfr]);
        }
    }

    float gam = gamma[0];
    float linv[4][2];
#pragma unroll
    for (int ifr = 0; ifr < 4; ifr++) {
        int i = i0 + wi * 64 + ifr * 16 + g;
        linv[ifr][0] = gam / g_l[(size_t)b * N_SP + i];
        linv[ifr][1] = gam / g_l[(size_t)b * N_SP + i + 8];
    }
#pragma unroll
    for (int ifr = 0; ifr < 4; ifr++) {
        int i = i0 + wi * 64 + ifr * 16 + g;
#pragma unroll
        for (int cfr = 0; cfr < 4; cfr++) {
            int c = c0 + wc * 32 + cfr * 8 + t4 * 2;
            size_t base = ((size_t)b * C_CH + c) * N_SP;
            out[base + i]            = acc[ifr][cfr][0] * linv[ifr][0] + xin[base + i];
            out[base + N_SP + i]     = acc[ifr][cfr][1] * linv[ifr][0] + xin[base + N_SP + i];
            out[base + i + 8]        = acc[ifr][cfr][2] * linv[ifr][1] + xin[base + i + 8];
            out[base + N_SP + i + 8] = acc[ifr][cfr][3] * linv[ifr][1] + xin[base + N_SP + i + 8];
        }
    }
}

// ---------------------------------------------------------------------------
extern "C" void kernel_launch(void* const* d_in, const int* in_sizes, int n_in,
                              void* d_out, int out_size)
{
    const float* x  = (const float*)d_in[0];
    const float* Wq = (const float*)d_in[1];
    const float* bq = (const float*)d_in[2];
    const float* Wk = (const float*)d_in[3];
    const float* bk = (const float*)d_in[4];
    const float* Wv = (const float*)d_in[5];
    const float* bv = (const float*)d_in[6];
    const float* gm = (const float*)d_in[7];
    float* out = (float*)d_out;

    static cudaStream_t s1 = nullptr, s2 = nullptr, s3 = nullptr;
    static cudaEvent_t evFork = nullptr, evPV = nullptr, evEnd1 = nullptr, evEnd2 = nullptr;
    static cudaEvent_t evS[4], evM[4];
    if (!s1) {
        cudaStreamCreateWithFlags(&s1, cudaStreamNonBlocking);
        cudaStreamCreateWithFlags(&s2, cudaStreamNonBlocking);
        cudaStreamCreateWithFlags(&s3, cudaStreamNonBlocking);
        cudaEventCreateWithFlags(&evFork, cudaEventDisableTiming);
        cudaEventCreateWithFlags(&evPV, cudaEventDisableTiming);
        cudaEventCreateWithFlags(&evEnd1, cudaEventDisableTiming);
        cudaEventCreateWithFlags(&evEnd2, cudaEventDisableTiming);
        for (int b = 0; b < 4; b++) {
            cudaEventCreateWithFlags(&evS[b], cudaEventDisableTiming);
            cudaEventCreateWithFlags(&evM[b], cudaEventDisableTiming);
        }
        cudaFuncSetAttribute(projqk_kernel, cudaFuncAttributeMaxDynamicSharedMemorySize, 98304);
        cudaFuncSetAttribute(projv_kernel,  cudaFuncAttributeMaxDynamicSharedMemorySize, 65536);
        cudaFuncSetAttribute(sgemm_kernel,  cudaFuncAttributeMaxDynamicSharedMemorySize, 65536);
        cudaFuncSetAttribute(pv_kernel,     cudaFuncAttributeMaxDynamicSharedMemorySize, 98304);
    }

    conv_kernel<<<9472, 256>>>(x, Wq, Wk, Wv);
    cudaEventRecord(evFork, 0);

    // s1: projv (only needed by pv), later reused for pv batches 2-3
    cudaStreamWaitEvent(s1, evFork, 0);
    projv_kernel<<<dim3(32, 4, 4), 256, 65536, s1>>>(bv);
    cudaEventRecord(evPV, s1);

    // main: projqk then per-batch sgemm; softmax per batch chases on s2
    projqk_kernel<<<dim3(32, 2, 4), 256, 98304>>>(bq, bk);
    for (int b = 0; b < 4; b++) {
        sgemm_kernel<<<dim3(32, 32), 256, 65536>>>(b);
        cudaEventRecord(evS[b], 0);
        cudaStreamWaitEvent(s2, evS[b], 0);
        softmax_kernel<<<4096, 256, 0, s2>>>(b);
        cudaEventRecord(evM[b], s2);
    }

    // s3: pv batches 0-1 as soon as their softmax is done
    cudaStreamWaitEvent(s3, evPV, 0);
    cudaStreamWaitEvent(s3, evM[0], 0);
    cudaStreamWaitEvent(s3, evM[1], 0);
    pv_kernel<<<dim3(4, 32, 2), 256, 98304, s3>>>(x, gm, out, 0);
    cudaEventRecord(evEnd1, s3);

    // s1 (free after projv): pv batches 2-3, concurrent with pv01
    cudaStreamWaitEvent(s1, evM[2], 0);
    cudaStreamWaitEvent(s1, evM[3], 0);
    pv_kernel<<<dim3(4, 32, 2), 256, 98304, s1>>>(x, gm, out, 2);
    cudaEventRecord(evEnd2, s1);

    cudaStreamWaitEvent(0, evEnd1, 0);
    cudaStreamWaitEvent(0, evEnd2, 0);
}

// round 17
// speedup vs baseline: 1.0466x; 1.0137x over previous
#include <cuda_runtime.h>
#include <cuda_fp16.h>
#include <cstdint>

#define N_SP 4096
#define C_CH 512
#define B_SZ 4

typedef unsigned long long u64;
typedef unsigned int u32;

__device__ __half g_xth[(size_t)B_SZ * N_SP * C_CH];
__device__ __half g_xtl[(size_t)B_SZ * N_SP * C_CH];
__device__ __half g_wqh[64 * C_CH], g_wql[64 * C_CH];
__device__ __half g_wkh[64 * C_CH], g_wkl[64 * C_CH];
__device__ __half g_wvh[C_CH * C_CH], g_wvl[C_CH * C_CH];
__device__ __half g_qh[(size_t)B_SZ * N_SP * 64];
__device__ __half g_ql[(size_t)B_SZ * N_SP * 64];
__device__ __half g_kh[(size_t)B_SZ * N_SP * 64];
__device__ __half g_kl[(size_t)B_SZ * N_SP * 64];
__device__ __half g_vh[(size_t)B_SZ * C_CH * N_SP];
__device__ float  g_S [(size_t)B_SZ * N_SP * N_SP];
__device__ __half g_P [(size_t)B_SZ * N_SP * N_SP];
__device__ float  g_l [(size_t)B_SZ * N_SP];

__device__ __forceinline__ u32 s2u(const void* p) { return (u32)__cvta_generic_to_shared(p); }
__device__ __forceinline__ void cp16(u32 d, const void* s) {
    asm volatile("cp.async.cg.shared.global [%0], [%1], 16;" :: "r"(d), "l"(s));
}
__device__ __forceinline__ void cp_commit() { asm volatile("cp.async.commit_group;"); }
__device__ __forceinline__ void cp_wait0()  { asm volatile("cp.async.wait_group 0;"); }
__device__ __forceinline__ void cp_wait1()  { asm volatile("cp.async.wait_group 1;"); }
__device__ __forceinline__ u32 sw128(u32 o) { return o ^ ((o >> 3) & 0x70); }

__device__ __forceinline__ void ldsm4(u32& r0, u32& r1, u32& r2, u32& r3, u32 a) {
    asm volatile("ldmatrix.sync.aligned.m8n8.x4.shared.b16 {%0,%1,%2,%3}, [%4];"
                 : "=r"(r0), "=r"(r1), "=r"(r2), "=r"(r3) : "r"(a));
}
__device__ __forceinline__ void ldsm2(u32& r0, u32& r1, u32 a) {
    asm volatile("ldmatrix.sync.aligned.m8n8.x2.shared.b16 {%0,%1}, [%2];"
                 : "=r"(r0), "=r"(r1) : "r"(a));
}
__device__ __forceinline__ void mma16816(float* d, const u32* a, const u32* b) {
    asm volatile("mma.sync.aligned.m16n8k16.row.col.f32.f16.f16.f32 "
                 "{%0,%1,%2,%3}, {%4,%5,%6,%7}, {%8,%9}, {%0,%1,%2,%3};"
                 : "+f"(d[0]), "+f"(d[1]), "+f"(d[2]), "+f"(d[3])
                 : "r"(a[0]), "r"(a[1]), "r"(a[2]), "r"(a[3]), "r"(b[0]), "r"(b[1]));
}
__device__ __forceinline__ void st_hl2(__half* ph, __half* pl, size_t a, float o0, float o1) {
    __half h0 = __float2half_rn(o0), h1 = __float2half_rn(o1);
    __half l0 = __float2half_rn(o0 - __half2float(h0));
    __half l1 = __float2half_rn(o1 - __half2float(h1));
    *(__half2*)(ph + a) = __halves2half2(h0, h1);
    *(__half2*)(pl + a) = __halves2half2(l0, l1);
}

// ---------------------------------------------------------------------------
// conv (merged): blocks 0..8191 transpose+split x; 8192..9471 split weights
// ---------------------------------------------------------------------------
__global__ __launch_bounds__(256) void conv_kernel(
    const float* __restrict__ x, const float* __restrict__ wq,
    const float* __restrict__ wk, const float* __restrict__ wv)
{
    __shared__ float tile[32][33];
    int bid = blockIdx.x;
    if (bid < 8192) {
        int tx = threadIdx.x & 31, ty = threadIdx.x >> 5;
        int n0 = (bid & 127) * 32, c0 = ((bid >> 7) & 15) * 32, b = bid >> 11;
#pragma unroll
        for (int k = 0; k < 4; k++)
            tile[ty + k * 8][tx] = x[((size_t)b * C_CH + c0 + ty + k * 8) * N_SP + n0 + tx];
        __syncthreads();
#pragma unroll
        for (int k = 0; k < 4; k++) {
            int n = ty + k * 8;
            float v = tile[tx][n];
            __half h = __float2half_rn(v);
            size_t a = ((size_t)b * N_SP + n0 + n) * C_CH + c0 + tx;
            g_xth[a] = h;
            g_xtl[a] = __float2half_rn(v - __half2float(h));
        }
    } else {
        int i = (bid - 8192) * 256 + threadIdx.x;
        const float* src; __half *dh, *dl; int off;
        if (i < 32768)        { src = wq; dh = g_wqh; dl = g_wql; off = i; }
        else if (i < 65536)   { src = wk; dh = g_wkh; dl = g_wkl; off = i - 32768; }
        else                  { src = wv; dh = g_wvh; dl = g_wvl; off = i - 65536; }
        float v = src[off];
        __half h = __float2half_rn(v);
        dh[off] = h;
        dl[off] = __float2half_rn(v - __half2float(h));
    }
}

// ---------------------------------------------------------------------------
// projqk: q/k[n][64] = x^T @ W^T + bias (3-term hi/lo HMMA)
// ---------------------------------------------------------------------------
__global__ __launch_bounds__(256) void projqk_kernel(
    const float* __restrict__ bq, const float* __restrict__ bk)
{
    extern __shared__ char smx[];
    u32 sb = s2u(smx);
    int t = threadIdx.x, wid = t >> 5, l = t & 31;
    int n0 = blockIdx.x * 128, which = blockIdx.y, b = blockIdx.z;

    const char* xh = (const char*)(g_xth + ((size_t)b * N_SP + n0) * C_CH);
    const char* xl = (const char*)(g_xtl + ((size_t)b * N_SP + n0) * C_CH);
    const char* wh = (const char*)(which ? g_wkh : g_wqh);
    const char* wl = (const char*)(which ? g_wkl : g_wql);
    const float* bias = which ? bk : bq;
    __half* oh = (which ? g_kh : g_qh) + ((size_t)b * N_SP + n0) * 64;
    __half* ol = (which ? g_kl : g_ql) + ((size_t)b * N_SP + n0) * 64;

    auto load = [&](int kc, int s) {
        u32 base = s * 49152;
#pragma unroll
        for (int k2 = 0; k2 < 4; k2++) {
            int z = t + k2 * 256, r = z >> 3, c = z & 7;
            u32 off = sw128(r * 128 + c * 16);
            size_t go = (size_t)r * 1024 + kc * 128 + c * 16;
            cp16(sb + base + off, xh + go);
            cp16(sb + base + 16384 + off, xl + go);
        }
#pragma unroll
        for (int k2 = 0; k2 < 2; k2++) {
            int z = t + k2 * 256, r = z >> 3, c = z & 7;
            u32 off = sw128(r * 128 + c * 16);
            size_t go = (size_t)r * 1024 + kc * 128 + c * 16;
            cp16(sb + base + 32768 + off, wh + go);
            cp16(sb + base + 40960 + off, wl + go);
        }
        cp_commit();
    };

    int wn = wid & 3, wm = wid >> 2;
    float acc[2][4][4];
#pragma unroll
    for (int i = 0; i < 2; i++)
#pragma unroll
        for (int j = 0; j < 4; j++)
#pragma unroll
            for (int p = 0; p < 4; p++) acc[i][j][p] = 0.f;

    load(0, 0);
    for (int kc = 0; kc < 8; kc++) {
        int s = kc & 1;
        if (kc + 1 < 8) { load(kc + 1, s ^ 1); cp_wait1(); }
        else cp_wait0();
        __syncthreads();
        u32 xb0 = sb + s * 49152, wb0 = xb0 + 32768;
#pragma unroll
        for (int ks = 0; ks < 4; ks++) {
            u32 ah[2][4], al[2][4], bh[4][2], bl[4][2];
#pragma unroll
            for (int ifr = 0; ifr < 2; ifr++) {
                u32 ro = (wn * 32 + ifr * 16 + (l & 15)) * 128 + ks * 32 + ((l >> 4) & 1) * 16;
                ldsm4(ah[ifr][0], ah[ifr][1], ah[ifr][2], ah[ifr][3], xb0 + sw128(ro));
                ldsm4(al[ifr][0], al[ifr][1], al[ifr][2], al[ifr][3], xb0 + 16384 + sw128(ro));
            }
#pragma unroll
            for (int jfr = 0; jfr < 4; jfr++) {
                u32 ro = (wm * 32 + jfr * 8 + (l & 7)) * 128 + ks * 32 + ((l >> 3) & 1) * 16;
                ldsm2(bh[jfr][0], bh[jfr][1], wb0 + sw128(ro));
                ldsm2(bl[jfr][0], bl[jfr][1], wb0 + 8192 + sw128(ro));
            }
#pragma unroll
            for (int ifr = 0; ifr < 2; ifr++)
#pragma unroll
                for (int jfr = 0; jfr < 4; jfr++) {
                    mma16816(acc[ifr][jfr], ah[ifr], bh[jfr]);
                    mma16816(acc[ifr][jfr], ah[ifr], bl[jfr]);
                    mma16816(acc[ifr][jfr], al[ifr], bh[jfr]);
                }
        }
        __syncthreads();
    }

    int g = l >> 2, t4 = l & 3;
#pragma unroll
    for (int ifr = 0; ifr < 2; ifr++) {
        int r0 = wn * 32 + ifr * 16 + g;
#pragma unroll
        for (int jfr = 0; jfr < 4; jfr++) {
            int m = wm * 32 + jfr * 8 + t4 * 2;
            float bv0 = bias[m], bv1 = bias[m + 1];
            st_hl2(oh, ol, (size_t)r0 * 64 + m,
                   acc[ifr][jfr][0] + bv0, acc[ifr][jfr][1] + bv1);
            st_hl2(oh, ol, (size_t)(r0 + 8) * 64 + m,
                   acc[ifr][jfr][2] + bv0, acc[ifr][jfr][3] + bv1);
        }
    }
}

// ---------------------------------------------------------------------------
// projv: v[c][n] = Wv @ x + bias (single-term fp16 HMMA). CTA: 128c x 128n.
// ---------------------------------------------------------------------------
__global__ __launch_bounds__(256) void projv_kernel(const float* __restrict__ bv)
{
    extern __shared__ char smx[];
    u32 sb = s2u(smx);
    int t = threadIdx.x, wid = t >> 5, l = t & 31;
    int n0 = blockIdx.x * 128, c0 = blockIdx.y * 128, b = blockIdx.z;

    const char* ap = (const char*)(g_wvh + (size_t)c0 * C_CH);
    const char* bp = (const char*)(g_xth + ((size_t)b * N_SP + n0) * C_CH);
    __half* vo = g_vh + ((size_t)b * C_CH + c0) * N_SP;

    auto load = [&](int kc, int s) {
        u32 base = s * 32768;
#pragma unroll
        for (int k2 = 0; k2 < 4; k2++) {
            int z = t + k2 * 256, r = z >> 3, c = z & 7;
            u32 off = sw128(r * 128 + c * 16);
            size_t go = (size_t)r * 1024 + kc * 128 + c * 16;
            cp16(sb + base + off, ap + go);
            cp16(sb + base + 16384 + off, bp + go);
        }
        cp_commit();
    };

    int wi = wid & 1, wj = wid >> 1;
    float acc[4][4][4];
#pragma unroll
    for (int i = 0; i < 4; i++)
#pragma unroll
        for (int j = 0; j < 4; j++)
#pragma unroll
            for (int p = 0; p < 4; p++) acc[i][j][p] = 0.f;

    load(0, 0);
    for (int kc = 0; kc < 8; kc++) {
        int s = kc & 1;
        if (kc + 1 < 8) { load(kc + 1, s ^ 1); cp_wait1(); }
        else cp_wait0();
        __syncthreads();
        u32 ab0 = sb + s * 32768, bb0 = ab0 + 16384;
#pragma unroll
        for (int ks = 0; ks < 4; ks++) {
            u32 af[4][4], bf[4][2];
#pragma unroll
            for (int ifr = 0; ifr < 4; ifr++) {
                u32 ro = (wi * 64 + ifr * 16 + (l & 15)) * 128 + ks * 32 + ((l >> 4) & 1) * 16;
                ldsm4(af[ifr][0], af[ifr][1], af[ifr][2], af[ifr][3], ab0 + sw128(ro));
            }
#pragma unroll
            for (int jfr = 0; jfr < 4; jfr++) {
                u32 ro = (wj * 32 + jfr * 8 + (l & 7)) * 128 + ks * 32 + ((l >> 3) & 1) * 16;
                ldsm2(bf[jfr][0], bf[jfr][1], bb0 + sw128(ro));
            }
#pragma unroll
            for (int ifr = 0; ifr < 4; ifr++)
#pragma unroll
                for (int jfr = 0; jfr < 4; jfr++)
                    mma16816(acc[ifr][jfr], af[ifr], bf[jfr]);
        }
        __syncthreads();
    }

    int g = l >> 2, t4 = l & 3;
#pragma unroll
    for (int ifr = 0; ifr < 4; ifr++) {
        int cl = wi * 64 + ifr * 16 + g;
        float b0 = bv[c0 + cl], b1 = bv[c0 + cl + 8];
#pragma unroll
        for (int jfr = 0; jfr < 4; jfr++) {
            int nl = n0 + wj * 32 + jfr * 8 + t4 * 2;
            *(__half2*)(vo + (size_t)cl * N_SP + nl) =
                __halves2half2(__float2half_rn(acc[ifr][jfr][0] + b0),
                               __float2half_rn(acc[ifr][jfr][1] + b0));
            *(__half2*)(vo + (size_t)(cl + 8) * N_SP + nl) =
                __halves2half2(__float2half_rn(acc[ifr][jfr][2] + b1),
                               __float2half_rn(acc[ifr][jfr][3] + b1));
        }
    }
}

// ---------------------------------------------------------------------------
// S-GEMM (per batch): S = q.k^T via 2-term hi/lo HMMA (qh.kh + qh.kl; the
// ql.kh term is dropped — ~2e-3 absolute on S, ~7e-5 on final output).
// CTA: 128i x 128j. QL tile no longer loaded (48KB smem).
// ---------------------------------------------------------------------------
__global__ __launch_bounds__(256, 2) void sgemm_kernel(int b)
{
    extern __shared__ char smx[];
    const u32 QH = 0, KH = 16384, KL = 32768;
    u32 sb = s2u(smx);
    int t = threadIdx.x, wid = t >> 5, l = t & 31;
    int j0 = blockIdx.x * 128, i0 = blockIdx.y * 128;

    const char* qhp = (const char*)(g_qh + ((size_t)b * N_SP + i0) * 64);
    const char* khp = (const char*)(g_kh + ((size_t)b * N_SP + j0) * 64);
    const char* klp = (const char*)(g_kl + ((size_t)b * N_SP + j0) * 64);

#pragma unroll
    for (int it = 0; it < 4; it++) {
        int z = t + it * 256, r = z >> 3, c = z & 7;
        u32 off = sw128(r * 128 + c * 16);
        int go = r * 128 + c * 16;
        cp16(sb + QH + off, qhp + go);
        cp16(sb + KH + off, khp + go);
        cp16(sb + KL + off, klp + go);
    }
    cp_commit(); cp_wait0();
    __syncthreads();

    int wi = wid & 1, wj = wid >> 1;
    int g = l >> 2, t4 = l & 3;

    float acc[4][4][4];
#pragma unroll
    for (int i = 0; i < 4; i++)
#pragma unroll
        for (int j = 0; j < 4; j++)
#pragma unroll
            for (int p = 0; p < 4; p++) acc[i][j][p] = 0.f;

    const u32 bb[2] = { KH, KL };

#pragma unroll
    for (int term = 0; term < 2; term++) {
#pragma unroll
        for (int ks = 0; ks < 4; ks++) {
            u32 af[4][4], bf[4][2];
#pragma unroll
            for (int ifr = 0; ifr < 4; ifr++) {
                u32 a = sb + QH + sw128((wi * 64 + ifr * 16 + (l & 15)) * 128
                                        + ks * 32 + ((l >> 4) & 1) * 16);
                ldsm4(af[ifr][0], af[ifr][1], af[ifr][2], af[ifr][3], a);
            }
#pragma unroll
            for (int jfr = 0; jfr < 4; jfr++) {
                u32 a = sb + bb[term] + sw128((wj * 32 + jfr * 8 + (l & 7)) * 128
                                              + ks * 32 + ((l >> 3) & 1) * 16);
                ldsm2(bf[jfr][0], bf[jfr][1], a);
            }
#pragma unroll
            for (int ifr = 0; ifr < 4; ifr++)
#pragma unroll
                for (int jfr = 0; jfr < 4; jfr++)
                    mma16816(acc[ifr][jfr], af[ifr], bf[jfr]);
        }
    }

    float* S = g_S + (size_t)b * N_SP * N_SP;
#pragma unroll
    for (int ifr = 0; ifr < 4; ifr++) {
        int r0 = i0 + wi * 64 + ifr * 16 + g;
#pragma unroll
        for (int jfr = 0; jfr < 4; jfr++) {
            int col = j0 + wj * 32 + jfr * 8 + t4 * 2;
            float2 d0 = { acc[ifr][jfr][0], acc[ifr][jfr][1] };
            float2 d1 = { acc[ifr][jfr][2], acc[ifr][jfr][3] };
            *(float2*)&S[(size_t)r0 * N_SP + col]       = d0;
            *(float2*)&S[(size_t)(r0 + 8) * N_SP + col] = d1;
        }
    }
}

// ---------------------------------------------------------------------------
// Softmax (per batch): one row per block.
// ---------------------------------------------------------------------------
__global__ __launch_bounds__(256) void softmax_kernel(int b)
{
    __shared__ float red[8];
    int i = blockIdx.x, t = threadIdx.x, wid = t >> 5;
    const float* S = g_S + ((size_t)b * N_SP + i) * N_SP;
    __half* P = g_P + ((size_t)b * N_SP + i) * N_SP;

    float4 v[4];
    float mx = -1e30f;
#pragma unroll
    for (int k = 0; k < 4; k++) {
        v[k] = *(const float4*)&S[(k * 256 + t) * 4];
        mx = fmaxf(mx, fmaxf(fmaxf(v[k].x, v[k].y), fmaxf(v[k].z, v[k].w)));
    }
#pragma unroll
    for (int w = 1; w < 32; w <<= 1) mx = fmaxf(mx, __shfl_xor_sync(~0u, mx, w));
    if ((t & 31) == 0) red[wid] = mx;
    __syncthreads();
    mx = red[0];
#pragma unroll
    for (int w = 1; w < 8; w++) mx = fmaxf(mx, red[w]);
    __syncthreads();

    float sum = 0.f;
#pragma unroll
    for (int k = 0; k < 4; k++) {
        __half h0 = __float2half_rn(__expf(v[k].x - mx));
        __half h1 = __float2half_rn(__expf(v[k].y - mx));
        __half h2 = __float2half_rn(__expf(v[k].z - mx));
        __half h3 = __float2half_rn(__expf(v[k].w - mx));
        sum += __half2float(h0) + __half2float(h1) + __half2float(h2) + __half2float(h3);
        *(__half2*)&P[(k * 256 + t) * 4]     = __halves2half2(h0, h1);
        *(__half2*)&P[(k * 256 + t) * 4 + 2] = __halves2half2(h2, h3);
    }
#pragma unroll
    for (int w = 1; w < 32; w <<= 1) sum += __shfl_xor_sync(~0u, sum, w);
    if ((t & 31) == 0) red[wid] = sum;
    __syncthreads();
    if (t == 0) {
        float s = 0.f;
#pragma unroll
        for (int w = 0; w < 8; w++) s += red[w];
        g_l[(size_t)b * N_SP + i] = s;
    }
}

// ---------------------------------------------------------------------------
// PV (2 batches per launch): feat = P.V^T. CTA: 128i x 128c, 3-stage pipeline.
// ---------------------------------------------------------------------------
__global__ __launch_bounds__(256, 2) void pv_kernel(
    const float* __restrict__ xin, const float* __restrict__ gamma,
    float* __restrict__ out, int b0)
{
    extern __shared__ char smx[];
    u32 sb = s2u(smx);
    int t = threadIdx.x, wid = t >> 5, l = t & 31;
    int c0 = blockIdx.x * 128, i0 = blockIdx.y * 128, b = b0 + blockIdx.z;

    const char* pp = (const char*)(g_P  + ((size_t)b * N_SP + i0) * N_SP);
    const char* vp = (const char*)(g_vh + ((size_t)b * C_CH + c0) * N_SP);

    auto load_chunk = [&](int jc) {
        int s = jc % 3;
        size_t jb = (size_t)jc * 128;
        u32 base = (u32)s * 32768;
#pragma unroll
        for (int it = 0; it < 4; it++) {
            int z = t + it * 256, r = z >> 3, c = z & 7;
            u32 off = sw128(r * 128 + c * 16);
            cp16(sb + base + off, pp + (size_t)r * 8192 + jb + c * 16);
            cp16(sb + base + 16384 + off, vp + (size_t)r * 8192 + jb + c * 16);
        }
        cp_commit();
    };

    int wi = wid & 1, wc = wid >> 1;
    int g = l >> 2, t4 = l & 3;
    int grp = l >> 3;
    int bhalf = grp & 1;
    int bsub  = grp >> 1;

    float acc[4][4][4];
#pragma unroll
    for (int i = 0; i < 4; i++)
#pragma unroll
        for (int j = 0; j < 4; j++)
#pragma unroll
            for (int p = 0; p < 4; p++) acc[i][j][p] = 0.f;

    load_chunk(0);
    load_chunk(1);
    for (int it = 0; it < 64; it++) {
        if (it + 1 < 64) cp_wait1(); else cp_wait0();
        __syncthreads();
        if (it + 2 < 64) load_chunk(it + 2);
        u32 base = sb + (u32)(it % 3) * 32768;
#pragma unroll
        for (int ks = 0; ks < 4; ks++) {
            u32 af[4][4], bf[4][2];
#pragma unroll
            for (int ifr = 0; ifr < 4; ifr++) {
                u32 a = base + sw128((wi * 64 + ifr * 16 + (l & 15)) * 128
                                     + ks * 32 + ((l >> 4) & 1) * 16);
                ldsm4(af[ifr][0], af[ifr][1], af[ifr][2], af[ifr][3], a);
            }
#pragma unroll
            for (int cp2 = 0; cp2 < 2; cp2++) {
                int cfr = cp2 * 2 + bsub;
                u32 a = base + 16384 + sw128((wc * 32 + cfr * 8 + (l & 7)) * 128
                                             + ks * 32 + bhalf * 16);
                ldsm4(bf[cp2 * 2][0], bf[cp2 * 2][1],
                      bf[cp2 * 2 + 1][0], bf[cp2 * 2 + 1][1], a);
            }
#pragma unroll
            for (int ifr = 0; ifr < 4; ifr++)
#pragma unroll
                for (int cfr = 0; cfr < 4; cfr++)
                    mma16816(acc[ifr][cfr], af[ifr], bf[cfr]);
        }
    }

    float gam = gamma[0];
    float linv[4][2];
#pragma unroll
    for (int ifr = 0; ifr < 4; ifr++) {
        int i = i0 + wi * 64 + ifr * 16 + g;
        linv[ifr][0] = gam / g_l[(size_t)b * N_SP + i];
        linv[ifr][1] = gam / g_l[(size_t)b * N_SP + i + 8];
    }
#pragma unroll
    for (int ifr = 0; ifr < 4; ifr++) {
        int i = i0 + wi * 64 + ifr * 16 + g;
#pragma unroll
        for (int cfr = 0; cfr < 4; cfr++) {
            int c = c0 + wc * 32 + cfr * 8 + t4 * 2;
            size_t base = ((size_t)b * C_CH + c) * N_SP;
            out[base + i]            = acc[ifr][cfr][0] * linv[ifr][0] + xin[base + i];
            out[base + N_SP + i]     = acc[ifr][cfr][1] * linv[ifr][0] + xin[base + N_SP + i];
            out[base + i + 8]        = acc[ifr][cfr][2] * linv[ifr][1] + xin[base + i + 8];
            out[base + N_SP + i + 8] = acc[ifr][cfr][3] * linv[ifr][1] + xin[base + N_SP + i + 8];
        }
    }
}

// ---------------------------------------------------------------------------
extern "C" void kernel_launch(void* const* d_in, const int* in_sizes, int n_in,
                              void* d_out, int out_size)
{
    const float* x  = (const float*)d_in[0];
    const float* Wq = (const float*)d_in[1];
    const float* bq = (const float*)d_in[2];
    const float* Wk = (const float*)d_in[3];
    const float* bk = (const float*)d_in[4];
    const float* Wv = (const float*)d_in[5];
    const float* bv = (const float*)d_in[6];
    const float* gm = (const float*)d_in[7];
    float* out = (float*)d_out;

    static cudaStream_t s1 = nullptr, s2 = nullptr, s3 = nullptr;
    static cudaEvent_t evFork = nullptr, evPV = nullptr, evEnd1 = nullptr, evEnd2 = nullptr;
    static cudaEvent_t evS[4], evM[4];
    if (!s1) {
        cudaStreamCreateWithFlags(&s1, cudaStreamNonBlocking);
        cudaStreamCreateWithFlags(&s2, cudaStreamNonBlocking);
        cudaStreamCreateWithFlags(&s3, cudaStreamNonBlocking);
        cudaEventCreateWithFlags(&evFork, cudaEventDisableTiming);
        cudaEventCreateWithFlags(&evPV, cudaEventDisableTiming);
        cudaEventCreateWithFlags(&evEnd1, cudaEventDisableTiming);
        cudaEventCreateWithFlags(&evEnd2, cudaEventDisableTiming);
        for (int b = 0; b < 4; b++) {
            cudaEventCreateWithFlags(&evS[b], cudaEventDisableTiming);
            cudaEventCreateWithFlags(&evM[b], cudaEventDisableTiming);
        }
        cudaFuncSetAttribute(projqk_kernel, cudaFuncAttributeMaxDynamicSharedMemorySize, 98304);
        cudaFuncSetAttribute(projv_kernel,  cudaFuncAttributeMaxDynamicSharedMemorySize, 65536);
        cudaFuncSetAttribute(sgemm_kernel,  cudaFuncAttributeMaxDynamicSharedMemorySize, 49152);
        cudaFuncSetAttribute(pv_kernel,     cudaFuncAttributeMaxDynamicSharedMemorySize, 98304);
    }

    conv_kernel<<<9472, 256>>>(x, Wq, Wk, Wv);
    cudaEventRecord(evFork, 0);

    // s1: projv (only needed by pv), later reused for pv batches 2-3
    cudaStreamWaitEvent(s1, evFork, 0);
    projv_kernel<<<dim3(32, 4, 4), 256, 65536, s1>>>(bv);
    cudaEventRecord(evPV, s1);

    // main: projqk then per-batch sgemm; softmax per batch chases on s2
    projqk_kernel<<<dim3(32, 2, 4), 256, 98304>>>(bq, bk);
    for (int b = 0; b < 4; b++) {
        sgemm_kernel<<<dim3(32, 32), 256, 49152>>>(b);
        cudaEventRecord(evS[b], 0);
        cudaStreamWaitEvent(s2, evS[b], 0);
        softmax_kernel<<<4096, 256, 0, s2>>>(b);
        cudaEventRecord(evM[b], s2);
    }

    // s3: pv batches 0-1 as soon as their softmax is done
    cudaStreamWaitEvent(s3, evPV, 0);
    cudaStreamWaitEvent(s3, evM[0], 0);
    cudaStreamWaitEvent(s3, evM[1], 0);
    pv_kernel<<<dim3(4, 32, 2), 256, 98304, s3>>>(x, gm, out, 0);
    cudaEventRecord(evEnd1, s3);

    // s1 (free after projv): pv batches 2-3, concurrent with pv01
    cudaStreamWaitEvent(s1, evM[2], 0);
    cudaStreamWaitEvent(s1, evM[3], 0);
    pv_kernel<<<dim3(4, 32, 2), 256, 98304, s1>>>(x, gm, out, 2);
    cudaEventRecord(evEnd2, s1);

    cudaStreamWaitEvent(0, evEnd1, 0);
    cudaStreamWaitEvent(0, evEnd2, 0);
}